// round 3
// baseline (speedup 1.0000x reference)
#include <cuda_runtime.h>
#include <cstdint>

#define NEXP  8
#define TOPK  2
#define NTOK  4096
#define HID   1024
#define INTER 3584

// ---------------------------------------------------------------------------
// Device scratch (static __device__ globals: the only legal scratch per rules)
// ---------------------------------------------------------------------------
__device__ int   g_count[NEXP];
__device__ int   g_tok[NEXP * NTOK];
__device__ float g_gate[NEXP * NTOK];
// H activations: per-expert region of NTOK rows x INTER cols (fp32). ~470 MB.
__device__ float g_H[(size_t)NEXP * NTOK * INTER];

// ---------------------------------------------------------------------------
// Routing: build per-expert token lists from expert_mask (NEXP, TOPK, NTOK)
// ---------------------------------------------------------------------------
__global__ void zero_counts_kernel() {
    if (threadIdx.x < NEXP) g_count[threadIdx.x] = 0;
}

__global__ void route_kernel(const int* __restrict__ mask,
                             const float* __restrict__ rw) {
    int idx = blockIdx.x * blockDim.x + threadIdx.x;
    if (idx >= NTOK * TOPK) return;
    int t = idx >> 1;
    int k = idx & 1;
#pragma unroll
    for (int e = 0; e < NEXP; e++) {
        if (mask[(e * TOPK + k) * NTOK + t] != 0) {
            int slot = atomicAdd(&g_count[e], 1);
            g_tok[e * NTOK + slot]  = t;
            g_gate[e * NTOK + slot] = rw[t * TOPK + k];
            return;
        }
    }
}

// ---------------------------------------------------------------------------
// GEMM1: H = silu(X_g @ W1_e) * (X_g @ W3_e)   per expert, gathered rows
// 128x128x16 tiles, 256 threads, 8x8 per-thread blocking, dual accumulators,
// double-buffered shared memory with register prefetch.
// ---------------------------------------------------------------------------
__global__ __launch_bounds__(256, 1)
void gemm1_kernel(const float* __restrict__ X,
                  const float* __restrict__ W1,
                  const float* __restrict__ W3) {
    const int e   = blockIdx.z;
    const int cnt = g_count[e];
    const int m0  = blockIdx.y * 128;
    if (m0 >= cnt) return;
    const int n0  = blockIdx.x * 128;

    __shared__ float As [2][16][128];
    __shared__ float B1s[2][16][128];
    __shared__ float B3s[2][16][128];

    const int tid = threadIdx.x;
    const int tx  = tid & 15;   // 0..15 -> 8 output cols each
    const int ty  = tid >> 4;   // 0..15 -> 8 output rows each

    // A tile load mapping: 128 rows x 16 k -> 2 threads/row, 2 float4 each
    const int a_row  = tid >> 1;
    const int a_kofs = (tid & 1) << 3;
    const int grow   = m0 + a_row;
    const int tok    = (grow < cnt) ? g_tok[e * NTOK + grow] : g_tok[e * NTOK];
    const float* aptr = X + (size_t)tok * HID + a_kofs;

    // B tile load mapping: 16 k-rows x 128 cols -> tid>>4 = k, tid&15 -> col*8
    const int b_kk = tid >> 4;
    const int b_c  = (tid & 15) << 3;
    const size_t wofs = (size_t)e * HID * INTER + (size_t)b_kk * INTER + n0 + b_c;
    const float* b1p = W1 + wofs;
    const float* b3p = W3 + wofs;

    float acc1[8][8];
    float acc3[8][8];
#pragma unroll
    for (int i = 0; i < 8; i++)
#pragma unroll
        for (int j = 0; j < 8; j++) { acc1[i][j] = 0.f; acc3[i][j] = 0.f; }

    // preload stage 0
    float4 av0  = *(const float4*)(aptr);
    float4 av1  = *(const float4*)(aptr + 4);
    float4 b1v0 = *(const float4*)(b1p);
    float4 b1v1 = *(const float4*)(b1p + 4);
    float4 b3v0 = *(const float4*)(b3p);
    float4 b3v1 = *(const float4*)(b3p + 4);
    {
        float* a = &As[0][a_kofs][0];
        a[0 * 128 + a_row] = av0.x; a[1 * 128 + a_row] = av0.y;
        a[2 * 128 + a_row] = av0.z; a[3 * 128 + a_row] = av0.w;
        a[4 * 128 + a_row] = av1.x; a[5 * 128 + a_row] = av1.y;
        a[6 * 128 + a_row] = av1.z; a[7 * 128 + a_row] = av1.w;
        *(float4*)&B1s[0][b_kk][b_c]     = b1v0;
        *(float4*)&B1s[0][b_kk][b_c + 4] = b1v1;
        *(float4*)&B3s[0][b_kk][b_c]     = b3v0;
        *(float4*)&B3s[0][b_kk][b_c + 4] = b3v1;
    }

    const int NK = HID / 16;  // 64
    for (int ks = 0; ks < NK; ks++) {
        __syncthreads();
        const int cur = ks & 1;
        if (ks + 1 < NK) {
            const float* ap = aptr + (ks + 1) * 16;
            av0 = *(const float4*)(ap);
            av1 = *(const float4*)(ap + 4);
            const float* p1 = b1p + (size_t)(ks + 1) * 16 * INTER;
            const float* p3 = b3p + (size_t)(ks + 1) * 16 * INTER;
            b1v0 = *(const float4*)(p1);
            b1v1 = *(const float4*)(p1 + 4);
            b3v0 = *(const float4*)(p3);
            b3v1 = *(const float4*)(p3 + 4);
        }
#pragma unroll 4
        for (int kk = 0; kk < 16; kk++) {
            float4 a0 = *(const float4*)&As [cur][kk][ty * 8];
            float4 a1 = *(const float4*)&As [cur][kk][ty * 8 + 4];
            float4 c0 = *(const float4*)&B1s[cur][kk][tx * 8];
            float4 c1 = *(const float4*)&B1s[cur][kk][tx * 8 + 4];
            float4 d0 = *(const float4*)&B3s[cur][kk][tx * 8];
            float4 d1 = *(const float4*)&B3s[cur][kk][tx * 8 + 4];
            float a[8]   = {a0.x, a0.y, a0.z, a0.w, a1.x, a1.y, a1.z, a1.w};
            float b1f[8] = {c0.x, c0.y, c0.z, c0.w, c1.x, c1.y, c1.z, c1.w};
            float b3f[8] = {d0.x, d0.y, d0.z, d0.w, d1.x, d1.y, d1.z, d1.w};
#pragma unroll
            for (int i = 0; i < 8; i++)
#pragma unroll
                for (int j = 0; j < 8; j++) {
                    acc1[i][j] += a[i] * b1f[j];
                    acc3[i][j] += a[i] * b3f[j];
                }
        }
        if (ks + 1 < NK) {
            const int nxt = cur ^ 1;
            float* a = &As[nxt][a_kofs][0];
            a[0 * 128 + a_row] = av0.x; a[1 * 128 + a_row] = av0.y;
            a[2 * 128 + a_row] = av0.z; a[3 * 128 + a_row] = av0.w;
            a[4 * 128 + a_row] = av1.x; a[5 * 128 + a_row] = av1.y;
            a[6 * 128 + a_row] = av1.z; a[7 * 128 + a_row] = av1.w;
            *(float4*)&B1s[nxt][b_kk][b_c]     = b1v0;
            *(float4*)&B1s[nxt][b_kk][b_c + 4] = b1v1;
            *(float4*)&B3s[nxt][b_kk][b_c]     = b3v0;
            *(float4*)&B3s[nxt][b_kk][b_c + 4] = b3v1;
        }
    }

    // Epilogue: h = silu(c1) * c3 -> g_H
    const size_t hbase = (size_t)e * NTOK * INTER;
#pragma unroll
    for (int i = 0; i < 8; i++) {
        const int r = m0 + ty * 8 + i;
        if (r < cnt) {
            float o[8];
#pragma unroll
            for (int j = 0; j < 8; j++) {
                float x = acc1[i][j];
                float s = x / (1.f + __expf(-x));
                o[j] = s * acc3[i][j];
            }
            float* dst = g_H + hbase + (size_t)r * INTER + n0 + tx * 8;
            *(float4*)dst       = make_float4(o[0], o[1], o[2], o[3]);
            *(float4*)(dst + 4) = make_float4(o[4], o[5], o[6], o[7]);
        }
    }
}

// ---------------------------------------------------------------------------
// GEMM2: Y = H_e @ W2_e, scaled by gate, atomically scattered to output
// ---------------------------------------------------------------------------
__global__ __launch_bounds__(256, 1)
void gemm2_kernel(const float* __restrict__ W2, float* __restrict__ out) {
    const int e   = blockIdx.z;
    const int cnt = g_count[e];
    const int m0  = blockIdx.y * 128;
    if (m0 >= cnt) return;
    const int n0  = blockIdx.x * 128;

    __shared__ float As[2][16][128];
    __shared__ float Bs[2][16][128];

    const int tid = threadIdx.x;
    const int tx  = tid & 15;
    const int ty  = tid >> 4;

    const int a_row  = tid >> 1;
    const int a_kofs = (tid & 1) << 3;
    const float* aptr = g_H + ((size_t)e * NTOK + m0 + a_row) * INTER + a_kofs;

    const int b_kk = tid >> 4;
    const int b_c  = (tid & 15) << 3;
    const float* bp = W2 + (size_t)e * INTER * HID + (size_t)b_kk * HID + n0 + b_c;

    float acc[8][8];
#pragma unroll
    for (int i = 0; i < 8; i++)
#pragma unroll
        for (int j = 0; j < 8; j++) acc[i][j] = 0.f;

    float4 av0 = *(const float4*)(aptr);
    float4 av1 = *(const float4*)(aptr + 4);
    float4 bv0 = *(const float4*)(bp);
    float4 bv1 = *(const float4*)(bp + 4);
    {
        float* a = &As[0][a_kofs][0];
        a[0 * 128 + a_row] = av0.x; a[1 * 128 + a_row] = av0.y;
        a[2 * 128 + a_row] = av0.z; a[3 * 128 + a_row] = av0.w;
        a[4 * 128 + a_row] = av1.x; a[5 * 128 + a_row] = av1.y;
        a[6 * 128 + a_row] = av1.z; a[7 * 128 + a_row] = av1.w;
        *(float4*)&Bs[0][b_kk][b_c]     = bv0;
        *(float4*)&Bs[0][b_kk][b_c + 4] = bv1;
    }

    const int NK = INTER / 16;  // 224
    for (int ks = 0; ks < NK; ks++) {
        __syncthreads();
        const int cur = ks & 1;
        if (ks + 1 < NK) {
            const float* ap = aptr + (ks + 1) * 16;
            av0 = *(const float4*)(ap);
            av1 = *(const float4*)(ap + 4);
            const float* p = bp + (size_t)(ks + 1) * 16 * HID;
            bv0 = *(const float4*)(p);
            bv1 = *(const float4*)(p + 4);
        }
#pragma unroll 4
        for (int kk = 0; kk < 16; kk++) {
            float4 a0 = *(const float4*)&As[cur][kk][ty * 8];
            float4 a1 = *(const float4*)&As[cur][kk][ty * 8 + 4];
            float4 c0 = *(const float4*)&Bs[cur][kk][tx * 8];
            float4 c1 = *(const float4*)&Bs[cur][kk][tx * 8 + 4];
            float a[8]  = {a0.x, a0.y, a0.z, a0.w, a1.x, a1.y, a1.z, a1.w};
            float bf[8] = {c0.x, c0.y, c0.z, c0.w, c1.x, c1.y, c1.z, c1.w};
#pragma unroll
            for (int i = 0; i < 8; i++)
#pragma unroll
                for (int j = 0; j < 8; j++)
                    acc[i][j] += a[i] * bf[j];
        }
        if (ks + 1 < NK) {
            const int nxt = cur ^ 1;
            float* a = &As[nxt][a_kofs][0];
            a[0 * 128 + a_row] = av0.x; a[1 * 128 + a_row] = av0.y;
            a[2 * 128 + a_row] = av0.z; a[3 * 128 + a_row] = av0.w;
            a[4 * 128 + a_row] = av1.x; a[5 * 128 + a_row] = av1.y;
            a[6 * 128 + a_row] = av1.z; a[7 * 128 + a_row] = av1.w;
            *(float4*)&Bs[nxt][b_kk][b_c]     = bv0;
            *(float4*)&Bs[nxt][b_kk][b_c + 4] = bv1;
        }
    }

    // Epilogue: gate-scale and scatter-add into output (<=2 adds per element,
    // onto zero, so the sum is bitwise deterministic regardless of ordering).
#pragma unroll
    for (int i = 0; i < 8; i++) {
        const int r = m0 + ty * 8 + i;
        if (r < cnt) {
            const int   tok  = g_tok[e * NTOK + r];
            const float gate = g_gate[e * NTOK + r];
            float* dst = out + (size_t)tok * HID + n0 + tx * 8;
#pragma unroll
            for (int j = 0; j < 8; j++)
                atomicAdd(&dst[j], gate * acc[i][j]);
        }
    }
}

// ---------------------------------------------------------------------------
// Launch
// ---------------------------------------------------------------------------
extern "C" void kernel_launch(void* const* d_in, const int* in_sizes, int n_in,
                              void* d_out, int out_size) {
    const int*   mask = (const int*)d_in[0];
    const float* X    = (const float*)d_in[1];
    const float* rw   = (const float*)d_in[2];
    const float* w1   = (const float*)d_in[3];
    const float* w2   = (const float*)d_in[4];
    const float* w3   = (const float*)d_in[5];
    float* out = (float*)d_out;

    cudaMemsetAsync(out, 0, (size_t)out_size * sizeof(float));
    zero_counts_kernel<<<1, 32>>>();
    route_kernel<<<(NTOK * TOPK + 255) / 256, 256>>>(mask, rw);

    dim3 g1(INTER / 128, NTOK / 128, NEXP);  // (28, 32, 8), most blocks early-exit
    gemm1_kernel<<<g1, 256>>>(X, w1, w3);

    dim3 g2(HID / 128, NTOK / 128, NEXP);    // (8, 32, 8)
    gemm2_kernel<<<g2, 256>>>(w2, out);
}

// round 6
// speedup vs baseline: 2.0352x; 2.0352x over previous
#include <cuda_runtime.h>
#include <cuda_bf16.h>
#include <cstdint>

#define NEXP  8
#define TOPK  2
#define NTOK  4096
#define HID   1024
#define INTER 3584
#define KC    32
#define RS    80      // smem row stride in bytes (conflict-free for frag LDS)

// ---------------------------------------------------------------------------
// Device scratch
// ---------------------------------------------------------------------------
__device__ int   g_count[NEXP];
__device__ int   g_tok[NEXP * NTOK];
__device__ float g_gate[NEXP * NTOK];
__device__ float g_H[(size_t)NEXP * NTOK * INTER];   // fp32 intermediate (rows>=cnt stay 0)

// ---------------------------------------------------------------------------
// Helpers
// ---------------------------------------------------------------------------
__device__ __forceinline__ void split2(float x, float y, uint32_t& h, uint32_t& l) {
    __nv_bfloat16 xh = __float2bfloat16(x);
    __nv_bfloat16 yh = __float2bfloat16(y);
    float xr = x - __bfloat162float(xh);
    float yr = y - __bfloat162float(yh);
    __nv_bfloat162 hh; hh.x = xh; hh.y = yh;
    __nv_bfloat162 ll = __floats2bfloat162_rn(xr, yr);
    h = *reinterpret_cast<uint32_t*>(&hh);
    l = *reinterpret_cast<uint32_t*>(&ll);
}

__device__ __forceinline__ void mma_bf16(float d[4], const uint32_t a[4], const uint32_t b[2]) {
    asm volatile(
        "mma.sync.aligned.m16n8k16.row.col.f32.bf16.bf16.f32 "
        "{%0,%1,%2,%3}, {%4,%5,%6,%7}, {%8,%9}, {%0,%1,%2,%3};"
        : "+f"(d[0]), "+f"(d[1]), "+f"(d[2]), "+f"(d[3])
        : "r"(a[0]), "r"(a[1]), "r"(a[2]), "r"(a[3]), "r"(b[0]), "r"(b[1]));
}

// ---------------------------------------------------------------------------
// Routing
// ---------------------------------------------------------------------------
__global__ void zero_counts_kernel() {
    if (threadIdx.x < NEXP) g_count[threadIdx.x] = 0;
}
__global__ void route_kernel(const int* __restrict__ mask,
                             const float* __restrict__ rw) {
    int idx = blockIdx.x * blockDim.x + threadIdx.x;
    if (idx >= NTOK * TOPK) return;
    int t = idx >> 1, k = idx & 1;
#pragma unroll
    for (int e = 0; e < NEXP; e++) {
        if (mask[(e * TOPK + k) * NTOK + t] != 0) {
            int slot = atomicAdd(&g_count[e], 1);
            g_tok[e * NTOK + slot]  = t;
            g_gate[e * NTOK + slot] = rw[t * TOPK + k];
            return;
        }
    }
}

// ---------------------------------------------------------------------------
// SMEM layouts
// ---------------------------------------------------------------------------
// GEMM1: A(128xKC) hi/lo + B1(64xKC) hi/lo + B3(64xKC) hi/lo, double-buffered
#define S1_AH   0
#define S1_AL   10240
#define S1_B1H  20480
#define S1_B1L  25600
#define S1_B3H  30720
#define S1_B3L  35840
#define S1_STAGE 40960
#define SMEM1   (2 * S1_STAGE)     // 81920 B

// GEMM2: A(128xKC) hi/lo + B(64xKC) hi/lo
#define S2_AH   0
#define S2_AL   10240
#define S2_BH   20480
#define S2_BL   25600
#define S2_STAGE 30720
#define SMEM2   (2 * S2_STAGE)     // 61440 B

// ---------------------------------------------------------------------------
// GEMM1: D1 = Xg @ W1, D3 = Xg @ W3, H = silu(D1)*D3   (bf16x3 via mma.sync)
// CTA 128x64, 8 warps (4m x 2n), warp tile 32x32
// ---------------------------------------------------------------------------
__global__ __launch_bounds__(256, 1)
void gemm1_kernel(const float* __restrict__ X,
                  const float* __restrict__ W1,
                  const float* __restrict__ W3) {
    const int e   = blockIdx.z;
    const int cnt = g_count[e];
    const int m0  = blockIdx.y * 128;
    if (m0 >= cnt) return;
    const int n0  = blockIdx.x * 64;

    extern __shared__ char smem[];
    const int tid  = threadIdx.x;
    const int lane = tid & 31;
    const int wid  = tid >> 5;
    const int wm   = wid & 3;
    const int wn   = wid >> 2;

    // --- staging source/dest for A: 2 threads/row, 16 k each ---
    const int a_row = tid >> 1;
    const int a_kh  = (tid & 1) << 4;
    int grow = m0 + a_row; if (grow >= cnt) grow = cnt - 1;
    const float* aptr = X + (size_t)g_tok[e * NTOK + grow] * HID + a_kh;
    const uint32_t a_dst = (uint32_t)(a_row * RS + a_kh * 2);

    // --- staging for B: 128 threads per matrix, thread owns (n, k-half) ---
    const int msel = tid >> 7;                 // 0 -> W1, 1 -> W3
    const int bt   = tid & 127;
    const int b_n  = bt & 63;
    const int b_kh = ((bt >> 6) & 1) << 4;
    const float* bptr = (msel ? W3 : W1) + (size_t)e * HID * INTER
                        + (size_t)b_kh * INTER + n0 + b_n;
    const uint32_t b_dH = (uint32_t)((msel ? S1_B3H : S1_B1H) + b_n * RS + b_kh * 2);
    const uint32_t b_dL = (uint32_t)((msel ? S1_B3L : S1_B1L) + b_n * RS + b_kh * 2);

    // --- compute-side fragment offsets ---
    const int g   = lane >> 2;
    const int tig = lane & 3;
    const uint32_t a_base = (uint32_t)((wm * 32 + g) * RS + tig * 4);
    const uint32_t b_base = (uint32_t)((wn * 32 + g) * RS + tig * 4);

    float acc1[2][4][4] = {};
    float acc3[2][4][4] = {};

    float4 av[4];
    float  bv[16];

    // ---- preload + store chunk 0 ----
#pragma unroll
    for (int j = 0; j < 4; j++) av[j] = *(const float4*)(aptr + j * 4);
#pragma unroll
    for (int q = 0; q < 16; q++) bv[q] = bptr[(size_t)q * INTER];
    {
        char* s = smem;
#pragma unroll
        for (int j = 0; j < 2; j++) {
            uint32_t h0, l0, h1, l1, h2, l2, h3, l3;
            split2(av[2*j].x,   av[2*j].y,   h0, l0);
            split2(av[2*j].z,   av[2*j].w,   h1, l1);
            split2(av[2*j+1].x, av[2*j+1].y, h2, l2);
            split2(av[2*j+1].z, av[2*j+1].w, h3, l3);
            *(uint4*)(s + S1_AH + a_dst + j * 16) = make_uint4(h0, h1, h2, h3);
            *(uint4*)(s + S1_AL + a_dst + j * 16) = make_uint4(l0, l1, l2, l3);
        }
#pragma unroll
        for (int j = 0; j < 2; j++) {
            uint32_t h[4], l[4];
#pragma unroll
            for (int q = 0; q < 4; q++)
                split2(bv[8*j + 2*q], bv[8*j + 2*q + 1], h[q], l[q]);
            *(uint4*)(s + b_dH + j * 16) = make_uint4(h[0], h[1], h[2], h[3]);
            *(uint4*)(s + b_dL + j * 16) = make_uint4(l[0], l[1], l[2], l[3]);
        }
    }
    __syncthreads();

    const int NC = HID / KC;   // 32
    for (int c = 0; c < NC; c++) {
        const bool pf = (c + 1 < NC);
        if (pf) {
            const float* ap = aptr + (c + 1) * KC;
#pragma unroll
            for (int j = 0; j < 4; j++) av[j] = *(const float4*)(ap + j * 4);
            const float* bp = bptr + (size_t)(c + 1) * KC * INTER;
#pragma unroll
            for (int q = 0; q < 16; q++) bv[q] = bp[(size_t)q * INTER];
        }

        const char* s = smem + (c & 1) * S1_STAGE;
#pragma unroll
        for (int ks = 0; ks < 2; ks++) {
            uint32_t aH[2][4], aL[2][4];
#pragma unroll
            for (int mi = 0; mi < 2; mi++) {
                uint32_t o = a_base + mi * 16 * RS + ks * 32;
                aH[mi][0] = *(const uint32_t*)(s + S1_AH + o);
                aH[mi][1] = *(const uint32_t*)(s + S1_AH + o + 8 * RS);
                aH[mi][2] = *(const uint32_t*)(s + S1_AH + o + 16);
                aH[mi][3] = *(const uint32_t*)(s + S1_AH + o + 8 * RS + 16);
                aL[mi][0] = *(const uint32_t*)(s + S1_AL + o);
                aL[mi][1] = *(const uint32_t*)(s + S1_AL + o + 8 * RS);
                aL[mi][2] = *(const uint32_t*)(s + S1_AL + o + 16);
                aL[mi][3] = *(const uint32_t*)(s + S1_AL + o + 8 * RS + 16);
            }
#pragma unroll
            for (int ni = 0; ni < 4; ni++) {
                uint32_t o = b_base + ni * 8 * RS + ks * 32;
                uint32_t bH[2], bL[2];
                // W1
                bH[0] = *(const uint32_t*)(s + S1_B1H + o);
                bH[1] = *(const uint32_t*)(s + S1_B1H + o + 16);
                bL[0] = *(const uint32_t*)(s + S1_B1L + o);
                bL[1] = *(const uint32_t*)(s + S1_B1L + o + 16);
#pragma unroll
                for (int mi = 0; mi < 2; mi++) {
                    mma_bf16(acc1[mi][ni], aH[mi], bH);
                    mma_bf16(acc1[mi][ni], aL[mi], bH);
                    mma_bf16(acc1[mi][ni], aH[mi], bL);
                }
                // W3
                bH[0] = *(const uint32_t*)(s + S1_B3H + o);
                bH[1] = *(const uint32_t*)(s + S1_B3H + o + 16);
                bL[0] = *(const uint32_t*)(s + S1_B3L + o);
                bL[1] = *(const uint32_t*)(s + S1_B3L + o + 16);
#pragma unroll
                for (int mi = 0; mi < 2; mi++) {
                    mma_bf16(acc3[mi][ni], aH[mi], bH);
                    mma_bf16(acc3[mi][ni], aL[mi], bH);
                    mma_bf16(acc3[mi][ni], aH[mi], bL);
                }
            }
        }

        if (pf) {
            char* sn = smem + ((c + 1) & 1) * S1_STAGE;
#pragma unroll
            for (int j = 0; j < 2; j++) {
                uint32_t h0, l0, h1, l1, h2, l2, h3, l3;
                split2(av[2*j].x,   av[2*j].y,   h0, l0);
                split2(av[2*j].z,   av[2*j].w,   h1, l1);
                split2(av[2*j+1].x, av[2*j+1].y, h2, l2);
                split2(av[2*j+1].z, av[2*j+1].w, h3, l3);
                *(uint4*)(sn + S1_AH + a_dst + j * 16) = make_uint4(h0, h1, h2, h3);
                *(uint4*)(sn + S1_AL + a_dst + j * 16) = make_uint4(l0, l1, l2, l3);
            }
#pragma unroll
            for (int j = 0; j < 2; j++) {
                uint32_t h[4], l[4];
#pragma unroll
                for (int q = 0; q < 4; q++)
                    split2(bv[8*j + 2*q], bv[8*j + 2*q + 1], h[q], l[q]);
                *(uint4*)(sn + b_dH + j * 16) = make_uint4(h[0], h[1], h[2], h[3]);
                *(uint4*)(sn + b_dL + j * 16) = make_uint4(l[0], l[1], l[2], l[3]);
            }
        }
        __syncthreads();
    }

    // ---- epilogue: silu(D1) * D3 -> g_H ----
    const size_t hrow = (size_t)e * NTOK;
#pragma unroll
    for (int mi = 0; mi < 2; mi++) {
#pragma unroll
        for (int half = 0; half < 2; half++) {
            const int r = m0 + wm * 32 + mi * 16 + g + half * 8;
            if (r < cnt) {
                float* dst = g_H + (hrow + r) * INTER + n0 + wn * 32 + tig * 2;
#pragma unroll
                for (int ni = 0; ni < 4; ni++) {
                    float x0 = acc1[mi][ni][half * 2 + 0];
                    float x1 = acc1[mi][ni][half * 2 + 1];
                    float2 o;
                    o.x = (x0 / (1.f + __expf(-x0))) * acc3[mi][ni][half * 2 + 0];
                    o.y = (x1 / (1.f + __expf(-x1))) * acc3[mi][ni][half * 2 + 1];
                    *(float2*)(dst + ni * 8) = o;
                }
            }
        }
    }
}

// ---------------------------------------------------------------------------
// GEMM2: out += gate * (H_e @ W2_e)     CTA 128x64, warp 32x32
// ---------------------------------------------------------------------------
__global__ __launch_bounds__(256, 2)
void gemm2_kernel(const float* __restrict__ W2, float* __restrict__ out) {
    const int e   = blockIdx.z;
    const int cnt = g_count[e];
    const int m0  = blockIdx.y * 128;
    if (m0 >= cnt) return;
    const int n0  = blockIdx.x * 64;

    extern __shared__ char smem[];
    const int tid  = threadIdx.x;
    const int lane = tid & 31;
    const int wid  = tid >> 5;
    const int wm   = wid & 3;
    const int wn   = wid >> 2;

    const int a_row = tid >> 1;
    const int a_kh  = (tid & 1) << 4;
    const float* aptr = g_H + ((size_t)e * NTOK + m0 + a_row) * INTER + a_kh;
    const uint32_t a_dst = (uint32_t)(a_row * RS + a_kh * 2);

    // B: 256 threads, thread owns (n, 8-k group)
    const int b_n  = tid & 63;
    const int b_kq = (tid >> 6) << 3;          // 0,8,16,24
    const float* bptr = W2 + (size_t)e * INTER * HID + (size_t)b_kq * HID + n0 + b_n;
    const uint32_t b_dst = (uint32_t)(b_n * RS + b_kq * 2);

    const int g   = lane >> 2;
    const int tig = lane & 3;
    const uint32_t a_base = (uint32_t)((wm * 32 + g) * RS + tig * 4);
    const uint32_t b_base = (uint32_t)((wn * 32 + g) * RS + tig * 4);

    float acc[2][4][4] = {};
    float4 av[4];
    float  bv[8];

#pragma unroll
    for (int j = 0; j < 4; j++) av[j] = *(const float4*)(aptr + j * 4);
#pragma unroll
    for (int q = 0; q < 8; q++) bv[q] = bptr[(size_t)q * HID];
    {
        char* s = smem;
#pragma unroll
        for (int j = 0; j < 2; j++) {
            uint32_t h0, l0, h1, l1, h2, l2, h3, l3;
            split2(av[2*j].x,   av[2*j].y,   h0, l0);
            split2(av[2*j].z,   av[2*j].w,   h1, l1);
            split2(av[2*j+1].x, av[2*j+1].y, h2, l2);
            split2(av[2*j+1].z, av[2*j+1].w, h3, l3);
            *(uint4*)(s + S2_AH + a_dst + j * 16) = make_uint4(h0, h1, h2, h3);
            *(uint4*)(s + S2_AL + a_dst + j * 16) = make_uint4(l0, l1, l2, l3);
        }
        uint32_t h[4], l[4];
#pragma unroll
        for (int q = 0; q < 4; q++) split2(bv[2*q], bv[2*q + 1], h[q], l[q]);
        *(uint4*)(s + S2_BH + b_dst) = make_uint4(h[0], h[1], h[2], h[3]);
        *(uint4*)(s + S2_BL + b_dst) = make_uint4(l[0], l[1], l[2], l[3]);
    }
    __syncthreads();

    const int NC = INTER / KC;   // 112
    for (int c = 0; c < NC; c++) {
        const bool pf = (c + 1 < NC);
        if (pf) {
            const float* ap = aptr + (c + 1) * KC;
#pragma unroll
            for (int j = 0; j < 4; j++) av[j] = *(const float4*)(ap + j * 4);
            const float* bp = bptr + (size_t)(c + 1) * KC * HID;
#pragma unroll
            for (int q = 0; q < 8; q++) bv[q] = bp[(size_t)q * HID];
        }

        const char* s = smem + (c & 1) * S2_STAGE;
#pragma unroll
        for (int ks = 0; ks < 2; ks++) {
            uint32_t aH[2][4], aL[2][4];
#pragma unroll
            for (int mi = 0; mi < 2; mi++) {
                uint32_t o = a_base + mi * 16 * RS + ks * 32;
                aH[mi][0] = *(const uint32_t*)(s + S2_AH + o);
                aH[mi][1] = *(const uint32_t*)(s + S2_AH + o + 8 * RS);
                aH[mi][2] = *(const uint32_t*)(s + S2_AH + o + 16);
                aH[mi][3] = *(const uint32_t*)(s + S2_AH + o + 8 * RS + 16);
                aL[mi][0] = *(const uint32_t*)(s + S2_AL + o);
                aL[mi][1] = *(const uint32_t*)(s + S2_AL + o + 8 * RS);
                aL[mi][2] = *(const uint32_t*)(s + S2_AL + o + 16);
                aL[mi][3] = *(const uint32_t*)(s + S2_AL + o + 8 * RS + 16);
            }
#pragma unroll
            for (int ni = 0; ni < 4; ni++) {
                uint32_t o = b_base + ni * 8 * RS + ks * 32;
                uint32_t bH[2], bL[2];
                bH[0] = *(const uint32_t*)(s + S2_BH + o);
                bH[1] = *(const uint32_t*)(s + S2_BH + o + 16);
                bL[0] = *(const uint32_t*)(s + S2_BL + o);
                bL[1] = *(const uint32_t*)(s + S2_BL + o + 16);
#pragma unroll
                for (int mi = 0; mi < 2; mi++) {
                    mma_bf16(acc[mi][ni], aH[mi], bH);
                    mma_bf16(acc[mi][ni], aL[mi], bH);
                    mma_bf16(acc[mi][ni], aH[mi], bL);
                }
            }
        }

        if (pf) {
            char* sn = smem + ((c + 1) & 1) * S2_STAGE;
#pragma unroll
            for (int j = 0; j < 2; j++) {
                uint32_t h0, l0, h1, l1, h2, l2, h3, l3;
                split2(av[2*j].x,   av[2*j].y,   h0, l0);
                split2(av[2*j].z,   av[2*j].w,   h1, l1);
                split2(av[2*j+1].x, av[2*j+1].y, h2, l2);
                split2(av[2*j+1].z, av[2*j+1].w, h3, l3);
                *(uint4*)(sn + S2_AH + a_dst + j * 16) = make_uint4(h0, h1, h2, h3);
                *(uint4*)(sn + S2_AL + a_dst + j * 16) = make_uint4(l0, l1, l2, l3);
            }
            uint32_t h[4], l[4];
#pragma unroll
            for (int q = 0; q < 4; q++) split2(bv[2*q], bv[2*q + 1], h[q], l[q]);
            *(uint4*)(sn + S2_BH + b_dst) = make_uint4(h[0], h[1], h[2], h[3]);
            *(uint4*)(sn + S2_BL + b_dst) = make_uint4(l[0], l[1], l[2], l[3]);
        }
        __syncthreads();
    }

    // ---- epilogue: gate-scale + atomic scatter (2 commutative adds onto 0) ----
#pragma unroll
    for (int mi = 0; mi < 2; mi++) {
#pragma unroll
        for (int half = 0; half < 2; half++) {
            const int r = m0 + wm * 32 + mi * 16 + g + half * 8;
            if (r < cnt) {
                const int   tk   = g_tok[e * NTOK + r];
                const float gate = g_gate[e * NTOK + r];
                float* dst = out + (size_t)tk * HID + n0 + wn * 32 + tig * 2;
#pragma unroll
                for (int ni = 0; ni < 4; ni++) {
                    atomicAdd(dst + ni * 8,     gate * acc[mi][ni][half * 2 + 0]);
                    atomicAdd(dst + ni * 8 + 1, gate * acc[mi][ni][half * 2 + 1]);
                }
            }
        }
    }
}

// ---------------------------------------------------------------------------
// Launch
// ---------------------------------------------------------------------------
extern "C" void kernel_launch(void* const* d_in, const int* in_sizes, int n_in,
                              void* d_out, int out_size) {
    const int*   mask = (const int*)d_in[0];
    const float* X    = (const float*)d_in[1];
    const float* rw   = (const float*)d_in[2];
    const float* w1   = (const float*)d_in[3];
    const float* w2   = (const float*)d_in[4];
    const float* w3   = (const float*)d_in[5];
    float* out = (float*)d_out;

    static bool attr_set = false;
    if (!attr_set) {
        cudaFuncSetAttribute(gemm1_kernel, cudaFuncAttributeMaxDynamicSharedMemorySize, SMEM1);
        cudaFuncSetAttribute(gemm2_kernel, cudaFuncAttributeMaxDynamicSharedMemorySize, SMEM2);
        attr_set = true;
    }

    cudaMemsetAsync(out, 0, (size_t)out_size * sizeof(float));
    zero_counts_kernel<<<1, 32>>>();
    route_kernel<<<(NTOK * TOPK + 255) / 256, 256>>>(mask, rw);

    dim3 g1(INTER / 64, NTOK / 128, NEXP);   // (56, 32, 8)
    gemm1_kernel<<<g1, 256, SMEM1>>>(X, w1, w3);

    dim3 g2(HID / 64, NTOK / 128, NEXP);     // (16, 32, 8)
    gemm2_kernel<<<g2, 256, SMEM2>>>(w2, out);
}

// round 7
// speedup vs baseline: 2.2189x; 1.0902x over previous
#include <cuda_runtime.h>
#include <cuda_bf16.h>
#include <cstdint>

#define NEXP  8
#define TOPK  2
#define NTOK  4096
#define HID   1024
#define INTER 3584
#define KC    32
#define RSA   160     // A smem row stride (bytes): 32 fp32 + 32B pad, conflict-free LDS.64
#define RSB   528     // B smem row stride (bytes): 128 fp32 + 16B pad, bank = 8*tig+g

// ---------------------------------------------------------------------------
// Device scratch
// ---------------------------------------------------------------------------
__device__ int   g_count[NEXP];
__device__ int   g_tok[NEXP * NTOK];
__device__ float g_gate[NEXP * NTOK];
__device__ float g_H[(size_t)NEXP * NTOK * INTER];   // fp32; rows>=cnt stay 0 forever

// ---------------------------------------------------------------------------
// Helpers
// ---------------------------------------------------------------------------
__device__ __forceinline__ uint32_t smem_u32(const void* p) {
    uint32_t a;
    asm("{ .reg .u64 t; cvta.to.shared.u64 t, %1; cvt.u32.u64 %0, t; }"
        : "=r"(a) : "l"(p));
    return a;
}
__device__ __forceinline__ void cp16(uint32_t dst, const void* src) {
    asm volatile("cp.async.cg.shared.global [%0], [%1], 16;\n" :: "r"(dst), "l"(src));
}
__device__ __forceinline__ void cp_commit() {
    asm volatile("cp.async.commit_group;\n");
}
template <int N> __device__ __forceinline__ void cp_wait() {
    asm volatile("cp.async.wait_group %0;\n" :: "n"(N));
}

__device__ __forceinline__ void split2(float x, float y, uint32_t& h, uint32_t& l) {
    __nv_bfloat16 xh = __float2bfloat16(x);
    __nv_bfloat16 yh = __float2bfloat16(y);
    float xr = x - __bfloat162float(xh);
    float yr = y - __bfloat162float(yh);
    __nv_bfloat162 hh; hh.x = xh; hh.y = yh;
    __nv_bfloat162 ll = __floats2bfloat162_rn(xr, yr);
    h = *reinterpret_cast<uint32_t*>(&hh);
    l = *reinterpret_cast<uint32_t*>(&ll);
}

__device__ __forceinline__ void mma_bf16(float d[4], const uint32_t a[4], const uint32_t b[2]) {
    asm volatile(
        "mma.sync.aligned.m16n8k16.row.col.f32.bf16.bf16.f32 "
        "{%0,%1,%2,%3}, {%4,%5,%6,%7}, {%8,%9}, {%0,%1,%2,%3};"
        : "+f"(d[0]), "+f"(d[1]), "+f"(d[2]), "+f"(d[3])
        : "r"(a[0]), "r"(a[1]), "r"(a[2]), "r"(a[3]), "r"(b[0]), "r"(b[1]));
}

// ---------------------------------------------------------------------------
// Routing
// ---------------------------------------------------------------------------
__global__ void zero_counts_kernel() {
    if (threadIdx.x < NEXP) g_count[threadIdx.x] = 0;
}
__global__ void route_kernel(const int* __restrict__ mask,
                             const float* __restrict__ rw) {
    int idx = blockIdx.x * blockDim.x + threadIdx.x;
    if (idx >= NTOK * TOPK) return;
    int t = idx >> 1, k = idx & 1;
#pragma unroll
    for (int e = 0; e < NEXP; e++) {
        if (mask[(e * TOPK + k) * NTOK + t] != 0) {
            int slot = atomicAdd(&g_count[e], 1);
            g_tok[e * NTOK + slot]  = t;
            g_gate[e * NTOK + slot] = rw[t * TOPK + k];
            return;
        }
    }
}

// ---------------------------------------------------------------------------
// SMEM layouts (fp32 tiles, double-buffered)
// ---------------------------------------------------------------------------
#define S1_A     0
#define S1_B1    20480                 // 128 * RSA
#define S1_B3    (S1_B1 + 16896)       // + 32 * RSB
#define S1_STG   (S1_B3 + 16896)       // 54272
#define SMEM1    (2 * S1_STG)          // 108544

#define S2_A     0
#define S2_B     20480
#define S2_STG   (S2_B + 16896)        // 37376
#define SMEM2    (2 * S2_STG)          // 74752

// ---------------------------------------------------------------------------
// GEMM1: D1 = Xg @ W1, D3 = Xg @ W3, H = silu(D1)*D3
// CTA 128(M) x 128(N per matrix), 8 warps (2m x 4n), warp tile 64x32 per matrix
// ---------------------------------------------------------------------------
__global__ __launch_bounds__(256, 1)
void gemm1_kernel(const float* __restrict__ X,
                  const float* __restrict__ W1,
                  const float* __restrict__ W3) {
    const int e   = blockIdx.z;
    const int cnt = g_count[e];
    const int m0  = blockIdx.y * 128;
    if (m0 >= cnt) return;
    const int n0  = blockIdx.x * 128;

    extern __shared__ char smem[];
    const uint32_t sb = smem_u32(smem);
    const int tid  = threadIdx.x;
    const int lane = tid & 31;
    const int wid  = tid >> 5;
    const int wm   = wid & 1;          // 0..1 -> 64 rows
    const int wn   = wid >> 1;         // 0..3 -> 32 cols

    // ---- cp.async staging descriptors ----
    const float* asrc[4]; uint32_t adst[4];
#pragma unroll
    for (int i = 0; i < 4; i++) {
        int id = tid + i * 256;
        int r  = id >> 3, ko = (id & 7) * 4;
        int grow = m0 + r; if (grow >= cnt) grow = cnt - 1;
        asrc[i] = X + (size_t)g_tok[e * NTOK + grow] * HID + ko;
        adst[i] = (uint32_t)(S1_A + r * RSA + ko * 4);
    }
    const float* b1src[4]; const float* b3src[4]; uint32_t bdst[4];
    const size_t wbase = (size_t)e * HID * INTER + n0;
#pragma unroll
    for (int i = 0; i < 4; i++) {
        int id = tid + i * 256;
        int kr = id >> 5, no = (id & 31) * 4;
        b1src[i] = W1 + wbase + (size_t)kr * INTER + no;
        b3src[i] = W3 + wbase + (size_t)kr * INTER + no;
        bdst[i]  = (uint32_t)(kr * RSB + no * 4);
    }

    auto issue = [&](int c) {
        uint32_t so = sb + (uint32_t)((c & 1) * S1_STG);
#pragma unroll
        for (int i = 0; i < 4; i++) cp16(so + adst[i], asrc[i] + c * KC);
#pragma unroll
        for (int i = 0; i < 4; i++) cp16(so + S1_B1 + bdst[i], b1src[i] + (size_t)c * KC * INTER);
#pragma unroll
        for (int i = 0; i < 4; i++) cp16(so + S1_B3 + bdst[i], b3src[i] + (size_t)c * KC * INTER);
        cp_commit();
    };

    const int g   = lane >> 2;
    const int tig = lane & 3;
    const uint32_t aoff = (uint32_t)((wm * 64 + g) * RSA + tig * 8);
    const uint32_t boff = (uint32_t)(2 * tig * RSB + (wn * 32 + g) * 4);

    float acc1[4][4][4] = {};
    float acc3[4][4][4] = {};

    issue(0);

    const int NC = HID / KC;   // 32
    for (int c = 0; c < NC; c++) {
        if (c + 1 < NC) { issue(c + 1); cp_wait<1>(); }
        else            { cp_wait<0>(); }
        __syncthreads();
        const char* s = smem + (c & 1) * S1_STG;

#pragma unroll
        for (int ks = 0; ks < 2; ks++) {
            uint32_t aH[4][4], aL[4][4];
#pragma unroll
            for (int mi = 0; mi < 4; mi++) {
                const char* ap = s + S1_A + aoff + mi * (16 * RSA) + ks * 64;
                float2 p0 = *(const float2*)(ap);
                float2 p1 = *(const float2*)(ap + 8 * RSA);
                float2 p2 = *(const float2*)(ap + 32);
                float2 p3 = *(const float2*)(ap + 8 * RSA + 32);
                split2(p0.x, p0.y, aH[mi][0], aL[mi][0]);
                split2(p1.x, p1.y, aH[mi][1], aL[mi][1]);
                split2(p2.x, p2.y, aH[mi][2], aL[mi][2]);
                split2(p3.x, p3.y, aH[mi][3], aL[mi][3]);
            }
#pragma unroll
            for (int ni = 0; ni < 4; ni++) {
                {
                    const char* bp = s + S1_B1 + boff + ni * 32 + ks * (16 * RSB);
                    float f0 = *(const float*)(bp);
                    float f1 = *(const float*)(bp + RSB);
                    float f2 = *(const float*)(bp + 8 * RSB);
                    float f3 = *(const float*)(bp + 9 * RSB);
                    uint32_t bH[2], bL[2];
                    split2(f0, f1, bH[0], bL[0]);
                    split2(f2, f3, bH[1], bL[1]);
#pragma unroll
                    for (int mi = 0; mi < 4; mi++) {
                        mma_bf16(acc1[mi][ni], aH[mi], bH);
                        mma_bf16(acc1[mi][ni], aL[mi], bH);
                        mma_bf16(acc1[mi][ni], aH[mi], bL);
                    }
                }
                {
                    const char* bp = s + S1_B3 + boff + ni * 32 + ks * (16 * RSB);
                    float f0 = *(const float*)(bp);
                    float f1 = *(const float*)(bp + RSB);
                    float f2 = *(const float*)(bp + 8 * RSB);
                    float f3 = *(const float*)(bp + 9 * RSB);
                    uint32_t bH[2], bL[2];
                    split2(f0, f1, bH[0], bL[0]);
                    split2(f2, f3, bH[1], bL[1]);
#pragma unroll
                    for (int mi = 0; mi < 4; mi++) {
                        mma_bf16(acc3[mi][ni], aH[mi], bH);
                        mma_bf16(acc3[mi][ni], aL[mi], bH);
                        mma_bf16(acc3[mi][ni], aH[mi], bL);
                    }
                }
            }
        }
        __syncthreads();
    }

    // ---- epilogue: silu(D1) * D3 -> g_H ----
    const size_t hrow = (size_t)e * NTOK;
#pragma unroll
    for (int mi = 0; mi < 4; mi++) {
#pragma unroll
        for (int half = 0; half < 2; half++) {
            const int r = m0 + wm * 64 + mi * 16 + g + half * 8;
            if (r < cnt) {
                float* dst = g_H + (hrow + r) * INTER + n0 + wn * 32 + tig * 2;
#pragma unroll
                for (int ni = 0; ni < 4; ni++) {
                    float x0 = acc1[mi][ni][half * 2 + 0];
                    float x1 = acc1[mi][ni][half * 2 + 1];
                    float2 o;
                    o.x = (x0 / (1.f + __expf(-x0))) * acc3[mi][ni][half * 2 + 0];
                    o.y = (x1 / (1.f + __expf(-x1))) * acc3[mi][ni][half * 2 + 1];
                    *(float2*)(dst + ni * 8) = o;
                }
            }
        }
    }
}

// ---------------------------------------------------------------------------
// GEMM2: out += gate * (H_e @ W2_e)   CTA 128x128, warp tile 64x32
// ---------------------------------------------------------------------------
__global__ __launch_bounds__(256, 2)
void gemm2_kernel(const float* __restrict__ W2, float* __restrict__ out) {
    const int e   = blockIdx.z;
    const int cnt = g_count[e];
    const int m0  = blockIdx.y * 128;
    if (m0 >= cnt) return;
    const int n0  = blockIdx.x * 128;

    extern __shared__ char smem[];
    const uint32_t sb = smem_u32(smem);
    const int tid  = threadIdx.x;
    const int lane = tid & 31;
    const int wid  = tid >> 5;
    const int wm   = wid & 1;
    const int wn   = wid >> 1;

    const float* asrc[4]; uint32_t adst[4];
#pragma unroll
    for (int i = 0; i < 4; i++) {
        int id = tid + i * 256;
        int r  = id >> 3, ko = (id & 7) * 4;
        // rows >= cnt read zero rows of g_H (never written) -> contribute 0
        asrc[i] = g_H + ((size_t)e * NTOK + m0 + r) * INTER + ko;
        adst[i] = (uint32_t)(S2_A + r * RSA + ko * 4);
    }
    const float* bsrc[4]; uint32_t bdst[4];
    const size_t wbase = (size_t)e * INTER * HID + n0;
#pragma unroll
    for (int i = 0; i < 4; i++) {
        int id = tid + i * 256;
        int kr = id >> 5, no = (id & 31) * 4;
        bsrc[i] = W2 + wbase + (size_t)kr * HID + no;
        bdst[i] = (uint32_t)(S2_B + kr * RSB + no * 4);
    }

    auto issue = [&](int c) {
        uint32_t so = sb + (uint32_t)((c & 1) * S2_STG);
#pragma unroll
        for (int i = 0; i < 4; i++) cp16(so + adst[i], asrc[i] + c * KC);
#pragma unroll
        for (int i = 0; i < 4; i++) cp16(so + bdst[i], bsrc[i] + (size_t)c * KC * HID);
        cp_commit();
    };

    const int g   = lane >> 2;
    const int tig = lane & 3;
    const uint32_t aoff = (uint32_t)((wm * 64 + g) * RSA + tig * 8);
    const uint32_t boff = (uint32_t)(2 * tig * RSB + (wn * 32 + g) * 4);

    float acc[4][4][4] = {};

    issue(0);

    const int NC = INTER / KC;   // 112
    for (int c = 0; c < NC; c++) {
        if (c + 1 < NC) { issue(c + 1); cp_wait<1>(); }
        else            { cp_wait<0>(); }
        __syncthreads();
        const char* s = smem + (c & 1) * S2_STG;

#pragma unroll
        for (int ks = 0; ks < 2; ks++) {
            uint32_t aH[4][4], aL[4][4];
#pragma unroll
            for (int mi = 0; mi < 4; mi++) {
                const char* ap = s + S2_A + aoff + mi * (16 * RSA) + ks * 64;
                float2 p0 = *(const float2*)(ap);
                float2 p1 = *(const float2*)(ap + 8 * RSA);
                float2 p2 = *(const float2*)(ap + 32);
                float2 p3 = *(const float2*)(ap + 8 * RSA + 32);
                split2(p0.x, p0.y, aH[mi][0], aL[mi][0]);
                split2(p1.x, p1.y, aH[mi][1], aL[mi][1]);
                split2(p2.x, p2.y, aH[mi][2], aL[mi][2]);
                split2(p3.x, p3.y, aH[mi][3], aL[mi][3]);
            }
#pragma unroll
            for (int ni = 0; ni < 4; ni++) {
                const char* bp = s + S2_B + boff + ni * 32 + ks * (16 * RSB);
                float f0 = *(const float*)(bp);
                float f1 = *(const float*)(bp + RSB);
                float f2 = *(const float*)(bp + 8 * RSB);
                float f3 = *(const float*)(bp + 9 * RSB);
                uint32_t bH[2], bL[2];
                split2(f0, f1, bH[0], bL[0]);
                split2(f2, f3, bH[1], bL[1]);
#pragma unroll
                for (int mi = 0; mi < 4; mi++) {
                    mma_bf16(acc[mi][ni], aH[mi], bH);
                    mma_bf16(acc[mi][ni], aL[mi], bH);
                    mma_bf16(acc[mi][ni], aH[mi], bL);
                }
            }
        }
        __syncthreads();
    }

    // ---- epilogue: gate-scale + atomic scatter (2 commutative adds onto 0) ----
#pragma unroll
    for (int mi = 0; mi < 4; mi++) {
#pragma unroll
        for (int half = 0; half < 2; half++) {
            const int r = m0 + wm * 64 + mi * 16 + g + half * 8;
            if (r < cnt) {
                const int   tk   = g_tok[e * NTOK + r];
                const float gate = g_gate[e * NTOK + r];
                float* dst = out + (size_t)tk * HID + n0 + wn * 32 + tig * 2;
#pragma unroll
                for (int ni = 0; ni < 4; ni++) {
                    atomicAdd(dst + ni * 8,     gate * acc[mi][ni][half * 2 + 0]);
                    atomicAdd(dst + ni * 8 + 1, gate * acc[mi][ni][half * 2 + 1]);
                }
            }
        }
    }
}

// ---------------------------------------------------------------------------
// Launch
// ---------------------------------------------------------------------------
extern "C" void kernel_launch(void* const* d_in, const int* in_sizes, int n_in,
                              void* d_out, int out_size) {
    const int*   mask = (const int*)d_in[0];
    const float* X    = (const float*)d_in[1];
    const float* rw   = (const float*)d_in[2];
    const float* w1   = (const float*)d_in[3];
    const float* w2   = (const float*)d_in[4];
    const float* w3   = (const float*)d_in[5];
    float* out = (float*)d_out;

    static bool attr_set = false;
    if (!attr_set) {
        cudaFuncSetAttribute(gemm1_kernel, cudaFuncAttributeMaxDynamicSharedMemorySize, SMEM1);
        cudaFuncSetAttribute(gemm2_kernel, cudaFuncAttributeMaxDynamicSharedMemorySize, SMEM2);
        attr_set = true;
    }

    cudaMemsetAsync(out, 0, (size_t)out_size * sizeof(float));
    zero_counts_kernel<<<1, 32>>>();
    route_kernel<<<(NTOK * TOPK + 255) / 256, 256>>>(mask, rw);

    dim3 g1(INTER / 128, NTOK / 128, NEXP);   // (28, 32, 8)
    gemm1_kernel<<<g1, 256, SMEM1>>>(X, w1, w3);

    dim3 g2(HID / 128, NTOK / 128, NEXP);     // (8, 32, 8)
    gemm2_kernel<<<g2, 256, SMEM2>>>(w2, out);
}

// round 11
// speedup vs baseline: 2.3741x; 1.0699x over previous
#include <cuda_runtime.h>
#include <cuda_bf16.h>
#include <cstdint>

#define NEXP  8
#define TOPK  2
#define NTOK  4096
#define HID   1024
#define INTER 3584
#define KC    32

// ---------------------------------------------------------------------------
// Device scratch (zero-initialized globals)
// ---------------------------------------------------------------------------
__device__ int   g_count[NEXP];
__device__ int   g_tok[NEXP * NTOK];
__device__ float g_gate[NEXP * NTOK];

// pre-split operands (hi/lo bf16). Weights stored TRANSPOSED: [e][n][k], k-contig
__device__ __nv_bfloat16 g_xh[(size_t)NTOK * HID];
__device__ __nv_bfloat16 g_xl[(size_t)NTOK * HID];
__device__ __nv_bfloat16 g_w1h[(size_t)NEXP * INTER * HID];
__device__ __nv_bfloat16 g_w1l[(size_t)NEXP * INTER * HID];
__device__ __nv_bfloat16 g_w3h[(size_t)NEXP * INTER * HID];
__device__ __nv_bfloat16 g_w3l[(size_t)NEXP * INTER * HID];
__device__ __nv_bfloat16 g_w2h[(size_t)NEXP * HID * INTER];
__device__ __nv_bfloat16 g_w2l[(size_t)NEXP * HID * INTER];
// H intermediate, pre-split; rows >= cnt stay zero forever
__device__ __nv_bfloat16 g_hh[(size_t)NEXP * NTOK * INTER];
__device__ __nv_bfloat16 g_hl[(size_t)NEXP * NTOK * INTER];

// ---------------------------------------------------------------------------
// Helpers
// ---------------------------------------------------------------------------
__device__ __forceinline__ uint32_t smem_u32(const void* p) {
    uint32_t a;
    asm("{ .reg .u64 t; cvta.to.shared.u64 t, %1; cvt.u32.u64 %0, t; }"
        : "=r"(a) : "l"(p));
    return a;
}
__device__ __forceinline__ void cp16(uint32_t dst, const void* src) {
    asm volatile("cp.async.cg.shared.global [%0], [%1], 16;\n" :: "r"(dst), "l"(src));
}
__device__ __forceinline__ void cp_commit() {
    asm volatile("cp.async.commit_group;\n");
}
template <int N> __device__ __forceinline__ void cp_wait() {
    asm volatile("cp.async.wait_group %0;\n" :: "n"(N));
}
__device__ __forceinline__ void split2(float x, float y, uint32_t& h, uint32_t& l) {
    __nv_bfloat16 xh = __float2bfloat16(x);
    __nv_bfloat16 yh = __float2bfloat16(y);
    float xr = x - __bfloat162float(xh);
    float yr = y - __bfloat162float(yh);
    __nv_bfloat162 hh; hh.x = xh; hh.y = yh;
    __nv_bfloat162 ll = __floats2bfloat162_rn(xr, yr);
    h = *reinterpret_cast<uint32_t*>(&hh);
    l = *reinterpret_cast<uint32_t*>(&ll);
}
__device__ __forceinline__ void mma_bf16(float d[4], const uint32_t a[4], const uint32_t b[2]) {
    asm volatile(
        "mma.sync.aligned.m16n8k16.row.col.f32.bf16.bf16.f32 "
        "{%0,%1,%2,%3}, {%4,%5,%6,%7}, {%8,%9}, {%0,%1,%2,%3};"
        : "+f"(d[0]), "+f"(d[1]), "+f"(d[2]), "+f"(d[3])
        : "r"(a[0]), "r"(a[1]), "r"(a[2]), "r"(a[3]), "r"(b[0]), "r"(b[1]));
}
__device__ __forceinline__ void ldsm4(uint32_t r[4], uint32_t addr) {
    asm volatile("ldmatrix.sync.aligned.m8n8.x4.shared.b16 {%0,%1,%2,%3}, [%4];"
                 : "=r"(r[0]), "=r"(r[1]), "=r"(r[2]), "=r"(r[3]) : "r"(addr));
}
__device__ __forceinline__ void ldsm2(uint32_t r[2], uint32_t addr) {
    asm volatile("ldmatrix.sync.aligned.m8n8.x2.shared.b16 {%0,%1}, [%2];"
                 : "=r"(r[0]), "=r"(r[1]) : "r"(addr));
}

// swizzled byte offset of 16B chunk c in 64B row r
#define SWC(r, c) ((((c) ^ (((r) >> 1) & 3))) * 16)

// ---------------------------------------------------------------------------
// Routing
// ---------------------------------------------------------------------------
__global__ void zero_counts_kernel() {
    if (threadIdx.x < NEXP) g_count[threadIdx.x] = 0;
}
__global__ void route_kernel(const int* __restrict__ mask,
                             const float* __restrict__ rw) {
    int idx = blockIdx.x * blockDim.x + threadIdx.x;
    if (idx >= NTOK * TOPK) return;
    int t = idx >> 1, k = idx & 1;
#pragma unroll
    for (int e = 0; e < NEXP; e++) {
        if (mask[(e * TOPK + k) * NTOK + t] != 0) {
            int slot = atomicAdd(&g_count[e], 1);
            g_tok[e * NTOK + slot]  = t;
            g_gate[e * NTOK + slot] = rw[t * TOPK + k];
            return;
        }
    }
}

// ---------------------------------------------------------------------------
// Pre-pass: split X (already k-contiguous)
// ---------------------------------------------------------------------------
__global__ void split_x_kernel(const float* __restrict__ x) {
    size_t i = ((size_t)blockIdx.x * blockDim.x + threadIdx.x) * 2;
    float2 v = *(const float2*)(x + i);
    uint32_t h, l;
    split2(v.x, v.y, h, l);
    *(uint32_t*)&g_xh[i] = h;
    *(uint32_t*)&g_xl[i] = l;
}

// ---------------------------------------------------------------------------
// Pre-pass: transpose + split weights. src [e][K][N] fp32 -> dst [e][N][K] bf16
// W: 0=w1, 1=w3, 2=w2
// ---------------------------------------------------------------------------
template <int W>
__global__ void transpose_split_kernel(const float* __restrict__ src, int K, int N) {
    __shared__ float tile[32][33];
    const int e  = blockIdx.z;
    const int n0 = blockIdx.x * 32, k0 = blockIdx.y * 32;
    const int tx = threadIdx.x, ty = threadIdx.y;
    const float* s = src + ((size_t)e * K + k0) * N + n0;
#pragma unroll
    for (int j = 0; j < 4; j++)
        tile[ty + j * 8][tx] = s[(size_t)(ty + j * 8) * N + tx];
    __syncthreads();
    __nv_bfloat16* dh = (W == 0) ? g_w1h : (W == 1) ? g_w3h : g_w2h;
    __nv_bfloat16* dl = (W == 0) ? g_w1l : (W == 1) ? g_w3l : g_w2l;
    const int tid = ty * 32 + tx;
    const int kp  = tid & 15;
    const int nb  = tid >> 4;
#pragma unroll
    for (int it = 0; it < 2; it++) {
        int nl = nb + it * 16;
        uint32_t h, l;
        split2(tile[kp * 2][nl], tile[kp * 2 + 1][nl], h, l);
        size_t o = ((size_t)e * N + n0 + nl) * K + k0;
        ((uint32_t*)(dh + o))[kp] = h;
        ((uint32_t*)(dl + o))[kp] = l;
    }
}

// ---------------------------------------------------------------------------
// SMEM layouts: 64B rows, XOR-swizzled, double-buffered
// ---------------------------------------------------------------------------
#define S1_AH  0
#define S1_AL  8192
#define S1_B1H 16384
#define S1_B1L 24576
#define S1_B3H 32768
#define S1_B3L 40960
#define S1_STG 49152
#define SMEM1  (2 * S1_STG)    // 98304

#define S2_AH  0
#define S2_AL  8192
#define S2_BH  16384
#define S2_BL  24576
#define S2_STG 32768
#define SMEM2  (2 * S2_STG)    // 65536

// ---------------------------------------------------------------------------
// GEMM1: D1 = Xg@W1, D3 = Xg@W3, H = silu(D1)*D3 (split) -> g_hh/g_hl
// CTA 128x128, 8 warps (2m x 4n), warp 64x32 per matrix. Pure ldmatrix+mma loop.
// ---------------------------------------------------------------------------
__global__ __launch_bounds__(256, 1)
void gemm1_kernel() {
    const int e   = blockIdx.z;
    const int cnt = g_count[e];
    const int m0  = blockIdx.y * 128;
    if (m0 >= cnt) return;
    const int n0  = blockIdx.x * 128;

    extern __shared__ char smem[];
    const uint32_t sb = smem_u32(smem);
    const int tid = threadIdx.x, lane = tid & 31, wid = tid >> 5;
    const int wm = wid & 1, wn = wid >> 1;

    // staging map: thread -> (row, 2 chunks)
    const int srow = tid >> 1;
    const int sc0  = (tid & 1) * 2;
    int grow = m0 + srow; if (grow >= cnt) grow = cnt - 1;
    const size_t xoff = (size_t)g_tok[e * NTOK + grow] * HID + sc0 * 8;
    const size_t boff = ((size_t)(e * INTER + n0 + srow)) * HID + sc0 * 8;
    const uint32_t d0 = (uint32_t)(srow * 64 + SWC(srow, sc0));
    const uint32_t d1 = (uint32_t)(srow * 64 + SWC(srow, sc0 + 1));

    auto issue = [&](int c) {
        const uint32_t so = sb + (uint32_t)((c & 1) * S1_STG);
        const size_t ko = (size_t)c * KC;
        cp16(so + S1_AH  + d0, g_xh  + xoff + ko);
        cp16(so + S1_AH  + d1, g_xh  + xoff + ko + 8);
        cp16(so + S1_AL  + d0, g_xl  + xoff + ko);
        cp16(so + S1_AL  + d1, g_xl  + xoff + ko + 8);
        cp16(so + S1_B1H + d0, g_w1h + boff + ko);
        cp16(so + S1_B1H + d1, g_w1h + boff + ko + 8);
        cp16(so + S1_B1L + d0, g_w1l + boff + ko);
        cp16(so + S1_B1L + d1, g_w1l + boff + ko + 8);
        cp16(so + S1_B3H + d0, g_w3h + boff + ko);
        cp16(so + S1_B3H + d1, g_w3h + boff + ko + 8);
        cp16(so + S1_B3L + d0, g_w3l + boff + ko);
        cp16(so + S1_B3L + d1, g_w3l + boff + ko + 8);
        cp_commit();
    };

    // ldmatrix lane addressing
    const int rA = lane & 15, cA = lane >> 4, mA = (rA >> 1) & 3;
    const uint32_t aRow = (uint32_t)((wm * 64 + rA) * 64);
    const uint32_t swA0 = (uint32_t)(((cA) ^ mA) * 16);
    const uint32_t swA1 = (uint32_t)(((2 + cA) ^ mA) * 16);
    const int rB = lane & 7, cB = (lane >> 3) & 1, mB = (rB >> 1) & 3;
    const uint32_t bRow = (uint32_t)((wn * 32 + rB) * 64);
    const uint32_t swB0 = (uint32_t)(((cB) ^ mB) * 16);
    const uint32_t swB1 = (uint32_t)(((2 + cB) ^ mB) * 16);

    float acc1[4][4][4] = {};
    float acc3[4][4][4] = {};

    issue(0);
    const int NC = HID / KC;   // 32
    for (int c = 0; c < NC; c++) {
        if (c + 1 < NC) { issue(c + 1); cp_wait<1>(); }
        else            { cp_wait<0>(); }
        __syncthreads();
        const uint32_t s = sb + (uint32_t)((c & 1) * S1_STG);
#pragma unroll
        for (int ks = 0; ks < 2; ks++) {
            const uint32_t swa = ks ? swA1 : swA0;
            const uint32_t swb = ks ? swB1 : swB0;
            uint32_t ah[4][4], al[4][4];
#pragma unroll
            for (int mi = 0; mi < 4; mi++) {
                ldsm4(ah[mi], s + S1_AH + aRow + mi * 1024 + swa);
                ldsm4(al[mi], s + S1_AL + aRow + mi * 1024 + swa);
            }
#pragma unroll
            for (int ni = 0; ni < 4; ni++) {
                const uint32_t bo = bRow + ni * 512 + swb;
                uint32_t bh[2], bl[2];
                ldsm2(bh, s + S1_B1H + bo);
                ldsm2(bl, s + S1_B1L + bo);
#pragma unroll
                for (int mi = 0; mi < 4; mi++) {
                    mma_bf16(acc1[mi][ni], ah[mi], bh);
                    mma_bf16(acc1[mi][ni], al[mi], bh);
                    mma_bf16(acc1[mi][ni], ah[mi], bl);
                }
                ldsm2(bh, s + S1_B3H + bo);
                ldsm2(bl, s + S1_B3L + bo);
#pragma unroll
                for (int mi = 0; mi < 4; mi++) {
                    mma_bf16(acc3[mi][ni], ah[mi], bh);
                    mma_bf16(acc3[mi][ni], al[mi], bh);
                    mma_bf16(acc3[mi][ni], ah[mi], bl);
                }
            }
        }
        __syncthreads();
    }

    // epilogue: silu(D1)*D3, split, store
    const int g = lane >> 2, tig = lane & 3;
#pragma unroll
    for (int mi = 0; mi < 4; mi++)
#pragma unroll
    for (int half = 0; half < 2; half++) {
        const int r = m0 + wm * 64 + mi * 16 + g + half * 8;
        if (r < cnt) {
            const size_t base = ((size_t)e * NTOK + r) * INTER + n0 + wn * 32 + tig * 2;
#pragma unroll
            for (int ni = 0; ni < 4; ni++) {
                float x0 = acc1[mi][ni][half * 2 + 0];
                float x1 = acc1[mi][ni][half * 2 + 1];
                float h0 = (x0 / (1.f + __expf(-x0))) * acc3[mi][ni][half * 2 + 0];
                float h1 = (x1 / (1.f + __expf(-x1))) * acc3[mi][ni][half * 2 + 1];
                uint32_t hh, ll;
                split2(h0, h1, hh, ll);
                *(uint32_t*)&g_hh[base + ni * 8] = hh;
                *(uint32_t*)&g_hl[base + ni * 8] = ll;
            }
        }
    }
}

// ---------------------------------------------------------------------------
// GEMM2: out += gate * (H_e @ W2_e)
// ---------------------------------------------------------------------------
__global__ __launch_bounds__(256, 2)
void gemm2_kernel(float* __restrict__ out) {
    const int e   = blockIdx.z;
    const int cnt = g_count[e];
    const int m0  = blockIdx.y * 128;
    if (m0 >= cnt) return;
    const int n0  = blockIdx.x * 128;

    extern __shared__ char smem[];
    const uint32_t sb = smem_u32(smem);
    const int tid = threadIdx.x, lane = tid & 31, wid = tid >> 5;
    const int wm = wid & 1, wn = wid >> 1;

    const int srow = tid >> 1;
    const int sc0  = (tid & 1) * 2;
    // rows >= cnt read zero rows of g_hh/g_hl -> contribute 0
    const size_t aoff = ((size_t)e * NTOK + m0 + srow) * INTER + sc0 * 8;
    const size_t boff = ((size_t)(e * HID + n0 + srow)) * INTER + sc0 * 8;
    const uint32_t d0 = (uint32_t)(srow * 64 + SWC(srow, sc0));
    const uint32_t d1 = (uint32_t)(srow * 64 + SWC(srow, sc0 + 1));

    auto issue = [&](int c) {
        const uint32_t so = sb + (uint32_t)((c & 1) * S2_STG);
        const size_t ko = (size_t)c * KC;
        cp16(so + S2_AH + d0, g_hh  + aoff + ko);
        cp16(so + S2_AH + d1, g_hh  + aoff + ko + 8);
        cp16(so + S2_AL + d0, g_hl  + aoff + ko);
        cp16(so + S2_AL + d1, g_hl  + aoff + ko + 8);
        cp16(so + S2_BH + d0, g_w2h + boff + ko);
        cp16(so + S2_BH + d1, g_w2h + boff + ko + 8);
        cp16(so + S2_BL + d0, g_w2l + boff + ko);
        cp16(so + S2_BL + d1, g_w2l + boff + ko + 8);
        cp_commit();
    };

    const int rA = lane & 15, cA = lane >> 4, mA = (rA >> 1) & 3;
    const uint32_t aRow = (uint32_t)((wm * 64 + rA) * 64);
    const uint32_t swA0 = (uint32_t)(((cA) ^ mA) * 16);
    const uint32_t swA1 = (uint32_t)(((2 + cA) ^ mA) * 16);
    const int rB = lane & 7, cB = (lane >> 3) & 1, mB = (rB >> 1) & 3;
    const uint32_t bRow = (uint32_t)((wn * 32 + rB) * 64);
    const uint32_t swB0 = (uint32_t)(((cB) ^ mB) * 16);
    const uint32_t swB1 = (uint32_t)(((2 + cB) ^ mB) * 16);

    float acc[4][4][4] = {};

    issue(0);
    const int NC = INTER / KC;   // 112
    for (int c = 0; c < NC; c++) {
        if (c + 1 < NC) { issue(c + 1); cp_wait<1>(); }
        else            { cp_wait<0>(); }
        __syncthreads();
        const uint32_t s = sb + (uint32_t)((c & 1) * S2_STG);
#pragma unroll
        for (int ks = 0; ks < 2; ks++) {
            const uint32_t swa = ks ? swA1 : swA0;
            const uint32_t swb = ks ? swB1 : swB0;
            uint32_t ah[4][4], al[4][4];
#pragma unroll
            for (int mi = 0; mi < 4; mi++) {
                ldsm4(ah[mi], s + S2_AH + aRow + mi * 1024 + swa);
                ldsm4(al[mi], s + S2_AL + aRow + mi * 1024 + swa);
            }
#pragma unroll
            for (int ni = 0; ni < 4; ni++) {
                const uint32_t bo = bRow + ni * 512 + swb;
                uint32_t bh[2], bl[2];
                ldsm2(bh, s + S2_BH + bo);
                ldsm2(bl, s + S2_BL + bo);
#pragma unroll
                for (int mi = 0; mi < 4; mi++) {
                    mma_bf16(acc[mi][ni], ah[mi], bh);
                    mma_bf16(acc[mi][ni], al[mi], bh);
                    mma_bf16(acc[mi][ni], ah[mi], bl);
                }
            }
        }
        __syncthreads();
    }

    // epilogue: gate-scale + atomic scatter (2 commutative adds onto 0)
    const int g = lane >> 2, tig = lane & 3;
#pragma unroll
    for (int mi = 0; mi < 4; mi++)
#pragma unroll
    for (int half = 0; half < 2; half++) {
        const int r = m0 + wm * 64 + mi * 16 + g + half * 8;
        if (r < cnt) {
            const int   tk   = g_tok[e * NTOK + r];
            const float gate = g_gate[e * NTOK + r];
            float* dst = out + (size_t)tk * HID + n0 + wn * 32 + tig * 2;
#pragma unroll
            for (int ni = 0; ni < 4; ni++) {
                atomicAdd(dst + ni * 8,     gate * acc[mi][ni][half * 2 + 0]);
                atomicAdd(dst + ni * 8 + 1, gate * acc[mi][ni][half * 2 + 1]);
            }
        }
    }
}

// ---------------------------------------------------------------------------
// Launch
// ---------------------------------------------------------------------------
extern "C" void kernel_launch(void* const* d_in, const int* in_sizes, int n_in,
                              void* d_out, int out_size) {
    const int*   mask = (const int*)d_in[0];
    const float* X    = (const float*)d_in[1];
    const float* rw   = (const float*)d_in[2];
    const float* w1   = (const float*)d_in[3];
    const float* w2   = (const float*)d_in[4];
    const float* w3   = (const float*)d_in[5];
    float* out = (float*)d_out;

    cudaFuncSetAttribute(gemm1_kernel, cudaFuncAttributeMaxDynamicSharedMemorySize, SMEM1);
    cudaFuncSetAttribute(gemm2_kernel, cudaFuncAttributeMaxDynamicSharedMemorySize, SMEM2);

    cudaMemsetAsync(out, 0, (size_t)out_size * sizeof(float));
    zero_counts_kernel<<<1, 32>>>();
    route_kernel<<<(NTOK * TOPK + 255) / 256, 256>>>(mask, rw);

    split_x_kernel<<<(NTOK * HID) / 512, 256>>>(X);
    dim3 tb(32, 8);
    transpose_split_kernel<0><<<dim3(INTER / 32, HID / 32, NEXP), tb>>>(w1, HID, INTER);
    transpose_split_kernel<1><<<dim3(INTER / 32, HID / 32, NEXP), tb>>>(w3, HID, INTER);
    transpose_split_kernel<2><<<dim3(HID / 32, INTER / 32, NEXP), tb>>>(w2, INTER, HID);

    gemm1_kernel<<<dim3(INTER / 128, NTOK / 128, NEXP), 256, SMEM1>>>();
    gemm2_kernel<<<dim3(HID / 128, NTOK / 128, NEXP), 256, SMEM2>>>(out);
}